// round 12
// baseline (speedup 1.0000x reference)
#include <cuda_runtime.h>
#include <cuda_fp16.h>
#include <cstdint>

// LeakySNN, de-fused:
//  K1 cvt: x,W1 -> fp16 hi/lo split arrays
//  K2 gemm: x1 = x@W1^T + b1, 128x128 block tile, 32x64 warp tile, XOR-swizzled smem
//  K3 lif:  25-step recurrence, f32x2-packed, spk.W2 -> atomicAdd(out)
// Shapes fixed: B=32768, NI=256, NH=1024, NO=1, NUM_STEPS=25.

#define NIc     256
#define NHc     1024
#define BTOT    32768
#define NSTEPS  25
#define BM      128
#define BN      128
#define BK      32
#define NSTAGE  (NIc / BK)   // 8
#define PIPE    3

// stage regions (bytes): 128 rows x 64B each
#define R_AHI   0
#define R_ALO   8192
#define R_BHI   16384
#define R_BLO   24576
#define STG_B   32768
#define SMEM_TOTAL (PIPE * STG_B)   // 98304 -> 2 blocks/SM

typedef unsigned long long u64;

__device__ __half g_xhi[(size_t)BTOT * NIc];
__device__ __half g_xlo[(size_t)BTOT * NIc];
__device__ __half g_whi[(size_t)NHc * NIc];
__device__ __half g_wlo[(size_t)NHc * NIc];
__device__ float  g_x1[(size_t)BTOT * NHc];   // 128 MB scratch

__global__ void cvt_kernel(const float* __restrict__ src,
                           __half* __restrict__ hi, __half* __restrict__ lo,
                           int n4) {
    int i = blockIdx.x * blockDim.x + threadIdx.x;
    if (i >= n4) return;
    float4 v = *((const float4*)src + i);
    __half h0 = __float2half_rn(v.x), h1 = __float2half_rn(v.y);
    __half h2 = __float2half_rn(v.z), h3 = __float2half_rn(v.w);
    __half l0 = __float2half_rn(v.x - __half2float(h0));
    __half l1 = __float2half_rn(v.y - __half2float(h1));
    __half l2 = __float2half_rn(v.z - __half2float(h2));
    __half l3 = __float2half_rn(v.w - __half2float(h3));
    __half2* ph = (__half2*)(hi + (size_t)i * 4);
    __half2* pl = (__half2*)(lo + (size_t)i * 4);
    ph[0] = __halves2half2(h0, h1); ph[1] = __halves2half2(h2, h3);
    pl[0] = __halves2half2(l0, l1); pl[1] = __halves2half2(l2, l3);
}

__global__ void init_out_kernel(float* __restrict__ out,
                                const float* __restrict__ b2, int n) {
    int i = blockIdx.x * blockDim.x + threadIdx.x;
    if (i < n) out[i] = b2[0];
}

__device__ __forceinline__ uint32_t smem_u32(const void* p) {
    uint32_t a;
    asm("{ .reg .u64 t; cvta.to.shared.u64 t, %1; cvt.u32.u64 %0, t; }" : "=r"(a) : "l"(p));
    return a;
}

__device__ __forceinline__ void cpasync16(uint32_t dst, const void* src) {
    asm volatile("cp.async.ca.shared.global [%0], [%1], 16;"
                 :: "r"(dst), "l"(__cvta_generic_to_global(src)) : "memory");
}
#define CP_COMMIT() asm volatile("cp.async.commit_group;" ::: "memory")
#define CP_WAIT(n)  asm volatile("cp.async.wait_group %0;" :: "n"(n) : "memory")

#define MMA16816(C, A, B) \
    asm volatile("mma.sync.aligned.m16n8k16.row.col.f32.f16.f16.f32 " \
        "{%0,%1,%2,%3}, {%4,%5,%6,%7}, {%8,%9}, {%0,%1,%2,%3};" \
        : "+f"((C)[0]), "+f"((C)[1]), "+f"((C)[2]), "+f"((C)[3]) \
        : "r"((A)[0]), "r"((A)[1]), "r"((A)[2]), "r"((A)[3]), \
          "r"((B)[0]), "r"((B)[1]))

#define LDMATRIX_X4(R, addr) \
    asm volatile("ldmatrix.sync.aligned.m8n8.x4.shared.b16 {%0,%1,%2,%3}, [%4];" \
        : "=r"((R)[0]), "=r"((R)[1]), "=r"((R)[2]), "=r"((R)[3]) : "r"(addr))

// swizzled byte offset within a region: row has 4 16B chunks
__device__ __forceinline__ uint32_t swz(int row, int chunk) {
    return (uint32_t)(row * 64 + ((chunk ^ ((row >> 1) & 3)) << 4));
}

// ---------------- K2: GEMM ----------------
__global__ void __launch_bounds__(256, 2)
snn_gemm_kernel(const float* __restrict__ b1) {
    extern __shared__ __align__(16) char smem[];
    const uint32_t stg0 = smem_u32(smem);

    const int tid = threadIdx.x;
    const int l   = tid & 31;
    const int wid = tid >> 5;
    const int wm  = wid & 3;        // 4 warps x 32 rows
    const int wn  = wid >> 2;       // 2 warps x 64 cols
    const int h0  = blockIdx.x * BN;
    const int b0  = blockIdx.y * BM;

    // ---- cp.async staging: thread t -> row t>>1, chunks {2(t&1), 2(t&1)+1} ----
    const int crow  = tid >> 1;
    const int cpair = (tid & 1) * 2;
    const __half* pxh = g_xhi + (size_t)(b0 + crow) * NIc + cpair * 8;
    const __half* pxl = g_xlo + (size_t)(b0 + crow) * NIc + cpair * 8;
    const __half* pwh = g_whi + (size_t)(h0 + crow) * NIc + cpair * 8;
    const __half* pwl = g_wlo + (size_t)(h0 + crow) * NIc + cpair * 8;
    const uint32_t d0 = swz(crow, cpair);       // chunk cpair
    const uint32_t d1 = d0 ^ 16;                // chunk cpair+1 (bit0 toggle)

    auto issue_copy = [&](int s, int buf) {
        const uint32_t so = stg0 + (uint32_t)buf * STG_B;
        cpasync16(so + R_AHI + d0, pxh + s * BK);
        cpasync16(so + R_AHI + d1, pxh + s * BK + 8);
        cpasync16(so + R_ALO + d0, pxl + s * BK);
        cpasync16(so + R_ALO + d1, pxl + s * BK + 8);
        cpasync16(so + R_BHI + d0, pwh + s * BK);
        cpasync16(so + R_BHI + d1, pwh + s * BK + 8);
        cpasync16(so + R_BLO + d0, pwl + s * BK);
        cpasync16(so + R_BLO + d1, pwl + s * BK + 8);
        CP_COMMIT();
    };

    // ---- ldmatrix base addresses (stage 0, ks 0) ----
    const int mrow = l & 7, msel = l >> 3;
    uint32_t aHiAdr[2], aLoAdr[2];
#pragma unroll
    for (int mt = 0; mt < 2; mt++) {
        int row = wm * 32 + mt * 16 + (msel & 1) * 8 + mrow;
        int ch  = msel >> 1;                      // 16B chunk along k
        aHiAdr[mt] = stg0 + R_AHI + swz(row, ch);
        aLoAdr[mt] = stg0 + R_ALO + swz(row, ch);
    }
    uint32_t bHiAdr[4], bLoAdr[4];
#pragma unroll
    for (int p = 0; p < 4; p++) {
        int n  = wn * 64 + p * 16 + (msel >> 1) * 8 + mrow;
        int ch = msel & 1;
        bHiAdr[p] = stg0 + R_BHI + swz(n, ch);
        bLoAdr[p] = stg0 + R_BLO + swz(n, ch);
    }

    float c[2][8][4];
#pragma unroll
    for (int mt = 0; mt < 2; mt++)
#pragma unroll
        for (int nt = 0; nt < 8; nt++)
#pragma unroll
            for (int r = 0; r < 4; r++) c[mt][nt][r] = 0.0f;

    auto compute_stage = [&](int buf) {
        const uint32_t so = (uint32_t)buf * STG_B;
#pragma unroll
        for (int ks = 0; ks < 2; ks++) {
            const uint32_t kx = ks << 5;   // ks=1: chunk bit1 toggles -> addr ^ 32
            uint32_t ah[2][4], al[2][4], bh[4][4], bl[4][4];
#pragma unroll
            for (int mt = 0; mt < 2; mt++) {
                LDMATRIX_X4(ah[mt], (aHiAdr[mt] + so) ^ kx);
                LDMATRIX_X4(al[mt], (aLoAdr[mt] + so) ^ kx);
            }
#pragma unroll
            for (int p = 0; p < 4; p++)
                LDMATRIX_X4(bh[p], (bHiAdr[p] + so) ^ kx);
            // hi*hi
#pragma unroll
            for (int mt = 0; mt < 2; mt++)
#pragma unroll
                for (int nt = 0; nt < 8; nt++)
                    MMA16816(c[mt][nt], ah[mt], &bh[nt >> 1][(nt & 1) * 2]);
            // lo*hi
#pragma unroll
            for (int mt = 0; mt < 2; mt++)
#pragma unroll
                for (int nt = 0; nt < 8; nt++)
                    MMA16816(c[mt][nt], al[mt], &bh[nt >> 1][(nt & 1) * 2]);
#pragma unroll
            for (int p = 0; p < 4; p++)
                LDMATRIX_X4(bl[p], (bLoAdr[p] + so) ^ kx);
            // hi*lo
#pragma unroll
            for (int mt = 0; mt < 2; mt++)
#pragma unroll
                for (int nt = 0; nt < 8; nt++)
                    MMA16816(c[mt][nt], ah[mt], &bl[nt >> 1][(nt & 1) * 2]);
        }
    };

    issue_copy(0, 0);
    issue_copy(1, 1);
#pragma unroll 1
    for (int s = 0; s < NSTAGE; s++) {
        if (s == NSTAGE - 1) { CP_WAIT(0); } else { CP_WAIT(1); }
        __syncthreads();
        if (s + 2 < NSTAGE) issue_copy(s + 2, (s + 2) % PIPE);
        compute_stage(s % PIPE);
    }

    // ---- epilogue: x1 = c + b1 -> gmem ----
    const int lr = l >> 2, lq = (l & 3) * 2;
    float bb[8][2];
#pragma unroll
    for (int nt = 0; nt < 8; nt++) {
        bb[nt][0] = __ldg(&b1[h0 + wn * 64 + nt * 8 + lq]);
        bb[nt][1] = __ldg(&b1[h0 + wn * 64 + nt * 8 + lq + 1]);
    }
#pragma unroll
    for (int mt = 0; mt < 2; mt++)
#pragma unroll
        for (int rr = 0; rr < 2; rr++) {
            const size_t grow = (size_t)(b0 + wm * 32 + mt * 16 + rr * 8 + lr) * NHc;
#pragma unroll
            for (int nt = 0; nt < 8; nt++) {
                const int gcol = h0 + wn * 64 + nt * 8 + lq;
                float2 v = make_float2(c[mt][nt][rr * 2 + 0] + bb[nt][0],
                                       c[mt][nt][rr * 2 + 1] + bb[nt][1]);
                *(float2*)&g_x1[grow + gcol] = v;
            }
        }
}

// ---------------- K3: LIF recurrence (f32x2) + W2 reduce ----------------
__device__ __forceinline__ u64 pk2(float lo, float hi) {
    u64 r;
    asm("mov.b64 %0, {%1, %2};" : "=l"(r) : "f"(lo), "f"(hi));
    return r;
}
__device__ __forceinline__ void upk2(u64 v, float& lo, float& hi) {
    asm("mov.b64 {%0, %1}, %2;" : "=f"(lo), "=f"(hi) : "l"(v));
}
__device__ __forceinline__ u64 fma2(u64 a, u64 b, u64 c) {
    u64 d;
    asm("fma.rn.f32x2 %0, %1, %2, %3;" : "=l"(d) : "l"(a), "l"(b), "l"(c));
    return d;
}
__device__ __forceinline__ void add2(u64& d, u64 a) {
    asm("add.rn.f32x2 %0, %0, %1;" : "+l"(d) : "l"(a));
}
__device__ __forceinline__ float fset_gt(float a, float b) {
    float s;
    asm("set.gt.f32.f32 %0, %1, %2;" : "=f"(s) : "f"(a), "f"(b));
    return s;
}

__global__ void __launch_bounds__(256)
snn_lif_kernel(const float* __restrict__ W2,
               const float* __restrict__ beta_p,
               const float* __restrict__ thr,
               float* __restrict__ out) {
    const int gw   = (blockIdx.x * blockDim.x + threadIdx.x) >> 5;
    const int lane = threadIdx.x & 31;
    const int b    = gw >> 2;
    const int q    = gw & 3;
    const int hb   = q * 256 + lane * 8;

    const float beta = fminf(fmaxf(__ldg(beta_p), 0.0f), 1.0f);
    const u64 beta2 = pk2(beta, beta);

    float x1[8], thv[8];
    const float* px = g_x1 + (size_t)b * NHc + hb;
    *(float4*)&x1[0]  = *(const float4*)(px);
    *(float4*)&x1[4]  = *(const float4*)(px + 4);
    *(float4*)&thv[0] = *(const float4*)(thr + hb);
    *(float4*)&thv[4] = *(const float4*)(thr + hb + 4);

    u64 x12[4], nth2[4], m2[4], cnt2[4];
#pragma unroll
    for (int p = 0; p < 4; p++) {
        x12[p]  = pk2(x1[2 * p], x1[2 * p + 1]);
        nth2[p] = pk2(-thv[2 * p], -thv[2 * p + 1]);
        cnt2[p] = pk2(0.0f, 0.0f);
        // step 1 from mem0 = 0: reset = H(0 - thr)
        u64 sv = pk2(fset_gt(0.0f, thv[2 * p]), fset_gt(0.0f, thv[2 * p + 1]));
        m2[p] = fma2(sv, nth2[p], x12[p]);
    }
#pragma unroll 4
    for (int t = 1; t < NSTEPS; t++) {
#pragma unroll
        for (int p = 0; p < 4; p++) {
            float ma, mb;
            upk2(m2[p], ma, mb);
            u64 sv = pk2(fset_gt(ma, thv[2 * p]), fset_gt(mb, thv[2 * p + 1]));
            add2(cnt2[p], sv);
            m2[p] = fma2(beta2, m2[p], fma2(sv, nth2[p], x12[p]));
        }
    }
    float acc = 0.0f;
#pragma unroll
    for (int p = 0; p < 4; p++) {
        float ma, mb;
        upk2(m2[p], ma, mb);
        u64 sv = pk2(fset_gt(ma, thv[2 * p]), fset_gt(mb, thv[2 * p + 1]));
        add2(cnt2[p], sv);
        float ca, cb;
        upk2(cnt2[p], ca, cb);
        acc = fmaf(ca, __ldg(&W2[hb + 2 * p]), acc);
        acc = fmaf(cb, __ldg(&W2[hb + 2 * p + 1]), acc);
    }
#pragma unroll
    for (int off = 16; off > 0; off >>= 1)
        acc += __shfl_down_sync(0xffffffffu, acc, off);
    if (lane == 0) atomicAdd(&out[b], acc);
}

extern "C" void kernel_launch(void* const* d_in, const int* in_sizes, int n_in,
                              void* d_out, int out_size) {
    const float* x    = (const float*)d_in[0];
    const float* W1   = (const float*)d_in[1];
    const float* b1   = (const float*)d_in[2];
    const float* W2   = (const float*)d_in[3];
    const float* b2   = (const float*)d_in[4];
    const float* beta = (const float*)d_in[5];
    const float* thr  = (const float*)d_in[6];
    float* out = (float*)d_out;

    const int B = in_sizes[0] / NIc;  // 32768

    __half *xhi, *xlo, *whi, *wlo;
    cudaGetSymbolAddress((void**)&xhi, g_xhi);
    cudaGetSymbolAddress((void**)&xlo, g_xlo);
    cudaGetSymbolAddress((void**)&whi, g_whi);
    cudaGetSymbolAddress((void**)&wlo, g_wlo);

    const int nx4 = B * NIc / 4;
    const int nw4 = NHc * NIc / 4;
    cvt_kernel<<<(nx4 + 255) / 256, 256>>>(x, xhi, xlo, nx4);
    cvt_kernel<<<(nw4 + 255) / 256, 256>>>(W1, whi, wlo, nw4);
    init_out_kernel<<<(B + 255) / 256, 256>>>(out, b2, B);

    cudaFuncSetAttribute(snn_gemm_kernel,
                         cudaFuncAttributeMaxDynamicSharedMemorySize, SMEM_TOTAL);

    dim3 grid(NHc / BN, B / BM);   // (8, 256)
    snn_gemm_kernel<<<grid, 256, SMEM_TOTAL>>>(b1);

    const int warps = B * 4;       // one warp per (row, quarter)
    snn_lif_kernel<<<warps * 32 / 256, 256>>>(W2, beta, thr, out);
}

// round 13
// speedup vs baseline: 1.0557x; 1.0557x over previous
#include <cuda_runtime.h>
#include <cuda_fp16.h>
#include <cstdint>

// LeakySNN, de-fused:
//  K1 cvt: x,W1 -> fp16 hi/lo split arrays
//  K2 gemm: x1 = x@W1^T + b1, 128x128 block tile, 32x64 warp tile, XOR-swizzled smem,
//           LDSM/MMA interleaved, cp.async.cg (L1 bypass)
//  K3 lif:  25-step recurrence, f32x2-packed, spk.W2 -> atomicAdd(out)
// Shapes fixed: B=32768, NI=256, NH=1024, NO=1, NUM_STEPS=25.

#define NIc     256
#define NHc     1024
#define BTOT    32768
#define NSTEPS  25
#define BM      128
#define BN      128
#define BK      32
#define NSTAGE  (NIc / BK)   // 8
#define PIPE    3

// stage regions (bytes): 128 rows x 64B each
#define R_AHI   0
#define R_ALO   8192
#define R_BHI   16384
#define R_BLO   24576
#define STG_B   32768
#define SMEM_TOTAL (PIPE * STG_B)   // 98304 -> 2 blocks/SM

typedef unsigned long long u64;

__device__ __half g_xhi[(size_t)BTOT * NIc];
__device__ __half g_xlo[(size_t)BTOT * NIc];
__device__ __half g_whi[(size_t)NHc * NIc];
__device__ __half g_wlo[(size_t)NHc * NIc];
__device__ float  g_x1[(size_t)BTOT * NHc];   // 128 MB scratch

__global__ void cvt_kernel(const float* __restrict__ src,
                           __half* __restrict__ hi, __half* __restrict__ lo,
                           int n4) {
    int i = blockIdx.x * blockDim.x + threadIdx.x;
    if (i >= n4) return;
    float4 v = *((const float4*)src + i);
    __half h0 = __float2half_rn(v.x), h1 = __float2half_rn(v.y);
    __half h2 = __float2half_rn(v.z), h3 = __float2half_rn(v.w);
    __half l0 = __float2half_rn(v.x - __half2float(h0));
    __half l1 = __float2half_rn(v.y - __half2float(h1));
    __half l2 = __float2half_rn(v.z - __half2float(h2));
    __half l3 = __float2half_rn(v.w - __half2float(h3));
    __half2* ph = (__half2*)(hi + (size_t)i * 4);
    __half2* pl = (__half2*)(lo + (size_t)i * 4);
    ph[0] = __halves2half2(h0, h1); ph[1] = __halves2half2(h2, h3);
    pl[0] = __halves2half2(l0, l1); pl[1] = __halves2half2(l2, l3);
}

__global__ void init_out_kernel(float* __restrict__ out,
                                const float* __restrict__ b2, int n) {
    int i = blockIdx.x * blockDim.x + threadIdx.x;
    if (i < n) out[i] = b2[0];
}

__device__ __forceinline__ uint32_t smem_u32(const void* p) {
    uint32_t a;
    asm("{ .reg .u64 t; cvta.to.shared.u64 t, %1; cvt.u32.u64 %0, t; }" : "=r"(a) : "l"(p));
    return a;
}

__device__ __forceinline__ void cpasync16(uint32_t dst, const void* src) {
    asm volatile("cp.async.cg.shared.global [%0], [%1], 16;"
                 :: "r"(dst), "l"(__cvta_generic_to_global(src)) : "memory");
}
#define CP_COMMIT() asm volatile("cp.async.commit_group;" ::: "memory")
#define CP_WAIT(n)  asm volatile("cp.async.wait_group %0;" :: "n"(n) : "memory")

#define MMA16816(C, A, B) \
    asm volatile("mma.sync.aligned.m16n8k16.row.col.f32.f16.f16.f32 " \
        "{%0,%1,%2,%3}, {%4,%5,%6,%7}, {%8,%9}, {%0,%1,%2,%3};" \
        : "+f"((C)[0]), "+f"((C)[1]), "+f"((C)[2]), "+f"((C)[3]) \
        : "r"((A)[0]), "r"((A)[1]), "r"((A)[2]), "r"((A)[3]), \
          "r"((B)[0]), "r"((B)[1]))

#define LDMATRIX_X4(R, addr) \
    asm volatile("ldmatrix.sync.aligned.m8n8.x4.shared.b16 {%0,%1,%2,%3}, [%4];" \
        : "=r"((R)[0]), "=r"((R)[1]), "=r"((R)[2]), "=r"((R)[3]) : "r"(addr))

// swizzled byte offset within a region: row has 4 16B chunks
__device__ __forceinline__ uint32_t swz(int row, int chunk) {
    return (uint32_t)(row * 64 + ((chunk ^ ((row >> 1) & 3)) << 4));
}

// ---------------- K2: GEMM ----------------
__global__ void __launch_bounds__(256, 2)
snn_gemm_kernel(const float* __restrict__ b1) {
    extern __shared__ __align__(16) char smem[];
    const uint32_t stg0 = smem_u32(smem);

    const int tid = threadIdx.x;
    const int l   = tid & 31;
    const int wid = tid >> 5;
    const int wm  = wid & 3;        // 4 warps x 32 rows
    const int wn  = wid >> 2;       // 2 warps x 64 cols
    const int h0  = blockIdx.x * BN;
    const int b0  = blockIdx.y * BM;

    // ---- cp.async staging: thread t -> row t>>1, chunks {2(t&1), 2(t&1)+1} ----
    const int crow  = tid >> 1;
    const int cpair = (tid & 1) * 2;
    const __half* pxh = g_xhi + (size_t)(b0 + crow) * NIc + cpair * 8;
    const __half* pxl = g_xlo + (size_t)(b0 + crow) * NIc + cpair * 8;
    const __half* pwh = g_whi + (size_t)(h0 + crow) * NIc + cpair * 8;
    const __half* pwl = g_wlo + (size_t)(h0 + crow) * NIc + cpair * 8;
    const uint32_t d0 = swz(crow, cpair);       // chunk cpair
    const uint32_t d1 = d0 ^ 16;                // chunk cpair+1 (bit0 toggle)

    auto issue_copy = [&](int s, int buf) {
        const uint32_t so = stg0 + (uint32_t)buf * STG_B;
        cpasync16(so + R_AHI + d0, pxh + s * BK);
        cpasync16(so + R_AHI + d1, pxh + s * BK + 8);
        cpasync16(so + R_ALO + d0, pxl + s * BK);
        cpasync16(so + R_ALO + d1, pxl + s * BK + 8);
        cpasync16(so + R_BHI + d0, pwh + s * BK);
        cpasync16(so + R_BHI + d1, pwh + s * BK + 8);
        cpasync16(so + R_BLO + d0, pwl + s * BK);
        cpasync16(so + R_BLO + d1, pwl + s * BK + 8);
        CP_COMMIT();
    };

    // ---- ldmatrix base addresses (stage 0, ks 0) ----
    const int mrow = l & 7, msel = l >> 3;
    uint32_t aHiAdr[2], aLoAdr[2];
#pragma unroll
    for (int mt = 0; mt < 2; mt++) {
        int row = wm * 32 + mt * 16 + (msel & 1) * 8 + mrow;
        int ch  = msel >> 1;                      // 16B chunk along k
        aHiAdr[mt] = stg0 + R_AHI + swz(row, ch);
        aLoAdr[mt] = stg0 + R_ALO + swz(row, ch);
    }
    uint32_t bHiAdr[4], bLoAdr[4];
#pragma unroll
    for (int p = 0; p < 4; p++) {
        int n  = wn * 64 + p * 16 + (msel >> 1) * 8 + mrow;
        int ch = msel & 1;
        bHiAdr[p] = stg0 + R_BHI + swz(n, ch);
        bLoAdr[p] = stg0 + R_BLO + swz(n, ch);
    }

    float c[2][8][4];
#pragma unroll
    for (int mt = 0; mt < 2; mt++)
#pragma unroll
        for (int nt = 0; nt < 8; nt++)
#pragma unroll
            for (int r = 0; r < 4; r++) c[mt][nt][r] = 0.0f;

    auto compute_stage = [&](int buf) {
        const uint32_t so = (uint32_t)buf * STG_B;
#pragma unroll
        for (int ks = 0; ks < 2; ks++) {
            const uint32_t kx = ks << 5;   // ks=1: chunk bit1 toggles -> addr ^ 32
            uint32_t ah[2][4], al[2][4], bh[4][4], bl[4][4];
            // load hi operands first
#pragma unroll
            for (int mt = 0; mt < 2; mt++)
                LDMATRIX_X4(ah[mt], (aHiAdr[mt] + so) ^ kx);
#pragma unroll
            for (int p = 0; p < 4; p++)
                LDMATRIX_X4(bh[p], (bHiAdr[p] + so) ^ kx);
            // hi*hi MMAs run while al LDSM (issued right after) completes
#pragma unroll
            for (int mt = 0; mt < 2; mt++) {
                LDMATRIX_X4(al[mt], (aLoAdr[mt] + so) ^ kx);
#pragma unroll
                for (int nt = 0; nt < 8; nt++)
                    MMA16816(c[mt][nt], ah[mt], &bh[nt >> 1][(nt & 1) * 2]);
            }
            // lo*hi MMAs cover bl LDSM latency
#pragma unroll
            for (int mt = 0; mt < 2; mt++) {
                LDMATRIX_X4(bl[2 * mt],     (bLoAdr[2 * mt] + so) ^ kx);
                LDMATRIX_X4(bl[2 * mt + 1], (bLoAdr[2 * mt + 1] + so) ^ kx);
#pragma unroll
                for (int nt = 0; nt < 8; nt++)
                    MMA16816(c[mt][nt], al[mt], &bh[nt >> 1][(nt & 1) * 2]);
            }
            // hi*lo
#pragma unroll
            for (int mt = 0; mt < 2; mt++)
#pragma unroll
                for (int nt = 0; nt < 8; nt++)
                    MMA16816(c[mt][nt], ah[mt], &bl[nt >> 1][(nt & 1) * 2]);
        }
    };

    issue_copy(0, 0);
    issue_copy(1, 1);
#pragma unroll 1
    for (int s = 0; s < NSTAGE; s++) {
        if (s == NSTAGE - 1) { CP_WAIT(0); } else { CP_WAIT(1); }
        __syncthreads();
        if (s + 2 < NSTAGE) issue_copy(s + 2, (s + 2) % PIPE);
        compute_stage(s % PIPE);
    }

    // ---- epilogue: x1 = c + b1 -> gmem ----
    const int lr = l >> 2, lq = (l & 3) * 2;
    float bb[8][2];
#pragma unroll
    for (int nt = 0; nt < 8; nt++) {
        bb[nt][0] = __ldg(&b1[h0 + wn * 64 + nt * 8 + lq]);
        bb[nt][1] = __ldg(&b1[h0 + wn * 64 + nt * 8 + lq + 1]);
    }
#pragma unroll
    for (int mt = 0; mt < 2; mt++)
#pragma unroll
        for (int rr = 0; rr < 2; rr++) {
            const size_t grow = (size_t)(b0 + wm * 32 + mt * 16 + rr * 8 + lr) * NHc;
#pragma unroll
            for (int nt = 0; nt < 8; nt++) {
                const int gcol = h0 + wn * 64 + nt * 8 + lq;
                float2 v = make_float2(c[mt][nt][rr * 2 + 0] + bb[nt][0],
                                       c[mt][nt][rr * 2 + 1] + bb[nt][1]);
                *(float2*)&g_x1[grow + gcol] = v;
            }
        }
}

// ---------------- K3: LIF recurrence (f32x2) + W2 reduce ----------------
__device__ __forceinline__ u64 pk2(float lo, float hi) {
    u64 r;
    asm("mov.b64 %0, {%1, %2};" : "=l"(r) : "f"(lo), "f"(hi));
    return r;
}
__device__ __forceinline__ void upk2(u64 v, float& lo, float& hi) {
    asm("mov.b64 {%0, %1}, %2;" : "=f"(lo), "=f"(hi) : "l"(v));
}
__device__ __forceinline__ u64 fma2(u64 a, u64 b, u64 c) {
    u64 d;
    asm("fma.rn.f32x2 %0, %1, %2, %3;" : "=l"(d) : "l"(a), "l"(b), "l"(c));
    return d;
}
__device__ __forceinline__ void add2(u64& d, u64 a) {
    asm("add.rn.f32x2 %0, %0, %1;" : "+l"(d) : "l"(a));
}
__device__ __forceinline__ float fset_gt(float a, float b) {
    float s;
    asm("set.gt.f32.f32 %0, %1, %2;" : "=f"(s) : "f"(a), "f"(b));
    return s;
}

__global__ void __launch_bounds__(256)
snn_lif_kernel(const float* __restrict__ W2,
               const float* __restrict__ beta_p,
               const float* __restrict__ thr,
               float* __restrict__ out) {
    const int gw   = (blockIdx.x * blockDim.x + threadIdx.x) >> 5;
    const int lane = threadIdx.x & 31;
    const int b    = gw >> 2;
    const int q    = gw & 3;
    const int hb   = q * 256 + lane * 8;

    const float beta = fminf(fmaxf(__ldg(beta_p), 0.0f), 1.0f);
    const u64 beta2 = pk2(beta, beta);

    float x1[8], thv[8];
    const float* px = g_x1 + (size_t)b * NHc + hb;
    *(float4*)&x1[0]  = *(const float4*)(px);
    *(float4*)&x1[4]  = *(const float4*)(px + 4);
    *(float4*)&thv[0] = *(const float4*)(thr + hb);
    *(float4*)&thv[4] = *(const float4*)(thr + hb + 4);

    u64 x12[4], nth2[4], m2[4], cnt2[4];
#pragma unroll
    for (int p = 0; p < 4; p++) {
        x12[p]  = pk2(x1[2 * p], x1[2 * p + 1]);
        nth2[p] = pk2(-thv[2 * p], -thv[2 * p + 1]);
        cnt2[p] = pk2(0.0f, 0.0f);
        // step 1 from mem0 = 0: reset = H(0 - thr)
        u64 sv = pk2(fset_gt(0.0f, thv[2 * p]), fset_gt(0.0f, thv[2 * p + 1]));
        m2[p] = fma2(sv, nth2[p], x12[p]);
    }
#pragma unroll 4
    for (int t = 1; t < NSTEPS; t++) {
#pragma unroll
        for (int p = 0; p < 4; p++) {
            float ma, mb;
            upk2(m2[p], ma, mb);
            u64 sv = pk2(fset_gt(ma, thv[2 * p]), fset_gt(mb, thv[2 * p + 1]));
            add2(cnt2[p], sv);
            m2[p] = fma2(beta2, m2[p], fma2(sv, nth2[p], x12[p]));
        }
    }
    float acc = 0.0f;
#pragma unroll
    for (int p = 0; p < 4; p++) {
        float ma, mb;
        upk2(m2[p], ma, mb);
        u64 sv = pk2(fset_gt(ma, thv[2 * p]), fset_gt(mb, thv[2 * p + 1]));
        add2(cnt2[p], sv);
        float ca, cb;
        upk2(cnt2[p], ca, cb);
        acc = fmaf(ca, __ldg(&W2[hb + 2 * p]), acc);
        acc = fmaf(cb, __ldg(&W2[hb + 2 * p + 1]), acc);
    }
#pragma unroll
    for (int off = 16; off > 0; off >>= 1)
        acc += __shfl_down_sync(0xffffffffu, acc, off);
    if (lane == 0) atomicAdd(&out[b], acc);
}

extern "C" void kernel_launch(void* const* d_in, const int* in_sizes, int n_in,
                              void* d_out, int out_size) {
    const float* x    = (const float*)d_in[0];
    const float* W1   = (const float*)d_in[1];
    const float* b1   = (const float*)d_in[2];
    const float* W2   = (const float*)d_in[3];
    const float* b2   = (const float*)d_in[4];
    const float* beta = (const float*)d_in[5];
    const float* thr  = (const float*)d_in[6];
    float* out = (float*)d_out;

    const int B = in_sizes[0] / NIc;  // 32768

    __half *xhi, *xlo, *whi, *wlo;
    cudaGetSymbolAddress((void**)&xhi, g_xhi);
    cudaGetSymbolAddress((void**)&xlo, g_xlo);
    cudaGetSymbolAddress((void**)&whi, g_whi);
    cudaGetSymbolAddress((void**)&wlo, g_wlo);

    const int nx4 = B * NIc / 4;
    const int nw4 = NHc * NIc / 4;
    cvt_kernel<<<(nx4 + 255) / 256, 256>>>(x, xhi, xlo, nx4);
    cvt_kernel<<<(nw4 + 255) / 256, 256>>>(W1, whi, wlo, nw4);
    init_out_kernel<<<(B + 255) / 256, 256>>>(out, b2, B);

    cudaFuncSetAttribute(snn_gemm_kernel,
                         cudaFuncAttributeMaxDynamicSharedMemorySize, SMEM_TOTAL);

    dim3 grid(NHc / BN, B / BM);   // (8, 256)
    snn_gemm_kernel<<<grid, 256, SMEM_TOTAL>>>(b1);

    const int warps = B * 4;       // one warp per (row, quarter)
    snn_lif_kernel<<<warps * 32 / 256, 256>>>(W2, beta, thr, out);
}

// round 14
// speedup vs baseline: 1.1348x; 1.0750x over previous
#include <cuda_runtime.h>
#include <cuda_fp16.h>
#include <cstdint>

// LeakySNN, de-fused:
//  K1 cvt: x,W1 -> fp16 hi/lo split arrays
//  K2 gemm: x1 = x@W1^T + b1, 128x128 block tile, 32x64 warp tile, XOR-swizzled smem,
//           LDSM/MMA interleaved w/ cross-ks preload, cp.async.cg, fully unrolled stages
//  K3 lif:  25-step recurrence, f32x2-packed, block=2 rows, smem-reduced, direct store
// Shapes fixed: B=32768, NI=256, NH=1024, NO=1, NUM_STEPS=25.

#define NIc     256
#define NHc     1024
#define BTOT    32768
#define NSTEPS  25
#define BM      128
#define BN      128
#define BK      32
#define NSTAGE  (NIc / BK)   // 8
#define PIPE    3

// stage regions (bytes): 128 rows x 64B each
#define R_AHI   0
#define R_ALO   8192
#define R_BHI   16384
#define R_BLO   24576
#define STG_B   32768
#define SMEM_TOTAL (PIPE * STG_B)   // 98304 -> 2 blocks/SM

typedef unsigned long long u64;

__device__ __half g_xhi[(size_t)BTOT * NIc];
__device__ __half g_xlo[(size_t)BTOT * NIc];
__device__ __half g_whi[(size_t)NHc * NIc];
__device__ __half g_wlo[(size_t)NHc * NIc];
__device__ float  g_x1[(size_t)BTOT * NHc];   // 128 MB scratch

__global__ void cvt_kernel(const float* __restrict__ src,
                           __half* __restrict__ hi, __half* __restrict__ lo,
                           int n4) {
    int i = blockIdx.x * blockDim.x + threadIdx.x;
    if (i >= n4) return;
    float4 v = *((const float4*)src + i);
    __half h0 = __float2half_rn(v.x), h1 = __float2half_rn(v.y);
    __half h2 = __float2half_rn(v.z), h3 = __float2half_rn(v.w);
    __half l0 = __float2half_rn(v.x - __half2float(h0));
    __half l1 = __float2half_rn(v.y - __half2float(h1));
    __half l2 = __float2half_rn(v.z - __half2float(h2));
    __half l3 = __float2half_rn(v.w - __half2float(h3));
    __half2* ph = (__half2*)(hi + (size_t)i * 4);
    __half2* pl = (__half2*)(lo + (size_t)i * 4);
    ph[0] = __halves2half2(h0, h1); ph[1] = __halves2half2(h2, h3);
    pl[0] = __halves2half2(l0, l1); pl[1] = __halves2half2(l2, l3);
}

__device__ __forceinline__ uint32_t smem_u32(const void* p) {
    uint32_t a;
    asm("{ .reg .u64 t; cvta.to.shared.u64 t, %1; cvt.u32.u64 %0, t; }" : "=r"(a) : "l"(p));
    return a;
}

__device__ __forceinline__ void cpasync16(uint32_t dst, const void* src) {
    asm volatile("cp.async.cg.shared.global [%0], [%1], 16;"
                 :: "r"(dst), "l"(__cvta_generic_to_global(src)) : "memory");
}
#define CP_COMMIT() asm volatile("cp.async.commit_group;" ::: "memory")
#define CP_WAIT(n)  asm volatile("cp.async.wait_group %0;" :: "n"(n) : "memory")

#define MMA16816(C, A, B) \
    asm volatile("mma.sync.aligned.m16n8k16.row.col.f32.f16.f16.f32 " \
        "{%0,%1,%2,%3}, {%4,%5,%6,%7}, {%8,%9}, {%0,%1,%2,%3};" \
        : "+f"((C)[0]), "+f"((C)[1]), "+f"((C)[2]), "+f"((C)[3]) \
        : "r"((A)[0]), "r"((A)[1]), "r"((A)[2]), "r"((A)[3]), \
          "r"((B)[0]), "r"((B)[1]))

#define LDMATRIX_X4(R, addr) \
    asm volatile("ldmatrix.sync.aligned.m8n8.x4.shared.b16 {%0,%1,%2,%3}, [%4];" \
        : "=r"((R)[0]), "=r"((R)[1]), "=r"((R)[2]), "=r"((R)[3]) : "r"(addr))

// swizzled byte offset within a region: row has 4 16B chunks
__device__ __forceinline__ uint32_t swz(int row, int chunk) {
    return (uint32_t)(row * 64 + ((chunk ^ ((row >> 1) & 3)) << 4));
}

// ---------------- K2: GEMM ----------------
__global__ void __launch_bounds__(256, 2)
snn_gemm_kernel(const float* __restrict__ b1) {
    extern __shared__ __align__(16) char smem[];
    const uint32_t stg0 = smem_u32(smem);

    const int tid = threadIdx.x;
    const int l   = tid & 31;
    const int wid = tid >> 5;
    const int wm  = wid & 3;        // 4 warps x 32 rows
    const int wn  = wid >> 2;       // 2 warps x 64 cols
    const int h0  = blockIdx.x * BN;
    const int b0  = blockIdx.y * BM;

    // ---- cp.async staging: thread t -> row t>>1, chunks {2(t&1), 2(t&1)+1} ----
    const int crow  = tid >> 1;
    const int cpair = (tid & 1) * 2;
    const __half* pxh = g_xhi + (size_t)(b0 + crow) * NIc + cpair * 8;
    const __half* pxl = g_xlo + (size_t)(b0 + crow) * NIc + cpair * 8;
    const __half* pwh = g_whi + (size_t)(h0 + crow) * NIc + cpair * 8;
    const __half* pwl = g_wlo + (size_t)(h0 + crow) * NIc + cpair * 8;
    const uint32_t d0 = swz(crow, cpair);
    const uint32_t d1 = d0 ^ 16;

    auto issue_copy = [&](int s, uint32_t buf) {
        const uint32_t so = stg0 + buf * STG_B;
        cpasync16(so + R_AHI + d0, pxh + s * BK);
        cpasync16(so + R_AHI + d1, pxh + s * BK + 8);
        cpasync16(so + R_ALO + d0, pxl + s * BK);
        cpasync16(so + R_ALO + d1, pxl + s * BK + 8);
        cpasync16(so + R_BHI + d0, pwh + s * BK);
        cpasync16(so + R_BHI + d1, pwh + s * BK + 8);
        cpasync16(so + R_BLO + d0, pwl + s * BK);
        cpasync16(so + R_BLO + d1, pwl + s * BK + 8);
        CP_COMMIT();
    };

    // ---- ldmatrix base addresses (stage 0, ks 0) ----
    const int mrow = l & 7, msel = l >> 3;
    uint32_t aHiAdr[2], aLoAdr[2];
#pragma unroll
    for (int mt = 0; mt < 2; mt++) {
        int row = wm * 32 + mt * 16 + (msel & 1) * 8 + mrow;
        int ch  = msel >> 1;
        aHiAdr[mt] = stg0 + R_AHI + swz(row, ch);
        aLoAdr[mt] = stg0 + R_ALO + swz(row, ch);
    }
    uint32_t bHiAdr[4], bLoAdr[4];
#pragma unroll
    for (int p = 0; p < 4; p++) {
        int n  = wn * 64 + p * 16 + (msel >> 1) * 8 + mrow;
        int ch = msel & 1;
        bHiAdr[p] = stg0 + R_BHI + swz(n, ch);
        bLoAdr[p] = stg0 + R_BLO + swz(n, ch);
    }

    float c[2][8][4];
#pragma unroll
    for (int mt = 0; mt < 2; mt++)
#pragma unroll
        for (int nt = 0; nt < 8; nt++)
#pragma unroll
            for (int r = 0; r < 4; r++) c[mt][nt][r] = 0.0f;

    // Stage body: per-accumulator order is HH, LH, HL per ks (bit-identical to prior
    // rounds); LDSM placed so every batch after the first runs under MMA cover,
    // including ks=1's bh (preloaded during ks=0's HL batch).
    auto compute_stage = [&](uint32_t so) {
        uint32_t ah[2][4], al[2][4], bh[4][4], bl[4][4], bh1[4][4];
        // ---- ks = 0 ----
        LDMATRIX_X4(ah[0], aHiAdr[0] + so);
        LDMATRIX_X4(ah[1], aHiAdr[1] + so);
        LDMATRIX_X4(bh[0], bHiAdr[0] + so);
        LDMATRIX_X4(bh[1], bHiAdr[1] + so);
        LDMATRIX_X4(bh[2], bHiAdr[2] + so);
        LDMATRIX_X4(bh[3], bHiAdr[3] + so);
        // HH0 (al loads under cover)
        LDMATRIX_X4(al[0], aLoAdr[0] + so);
#pragma unroll
        for (int nt = 0; nt < 8; nt++)
            MMA16816(c[0][nt], ah[0], &bh[nt >> 1][(nt & 1) * 2]);
        LDMATRIX_X4(al[1], aLoAdr[1] + so);
#pragma unroll
        for (int nt = 0; nt < 8; nt++)
            MMA16816(c[1][nt], ah[1], &bh[nt >> 1][(nt & 1) * 2]);
        // LH0 (bl loads under cover)
        LDMATRIX_X4(bl[0], bLoAdr[0] + so);
        LDMATRIX_X4(bl[1], bLoAdr[1] + so);
#pragma unroll
        for (int nt = 0; nt < 8; nt++)
            MMA16816(c[0][nt], al[0], &bh[nt >> 1][(nt & 1) * 2]);
        LDMATRIX_X4(bl[2], bLoAdr[2] + so);
        LDMATRIX_X4(bl[3], bLoAdr[3] + so);
#pragma unroll
        for (int nt = 0; nt < 8; nt++)
            MMA16816(c[1][nt], al[1], &bh[nt >> 1][(nt & 1) * 2]);
        // HL0 (ks=1 bh preloaded under cover; bh0 dead here)
        LDMATRIX_X4(bh1[0], (bHiAdr[0] + so) ^ 32);
        LDMATRIX_X4(bh1[1], (bHiAdr[1] + so) ^ 32);
#pragma unroll
        for (int nt = 0; nt < 8; nt++)
            MMA16816(c[0][nt], ah[0], &bl[nt >> 1][(nt & 1) * 2]);
        LDMATRIX_X4(bh1[2], (bHiAdr[2] + so) ^ 32);
        LDMATRIX_X4(bh1[3], (bHiAdr[3] + so) ^ 32);
#pragma unroll
        for (int nt = 0; nt < 8; nt++)
            MMA16816(c[1][nt], ah[1], &bl[nt >> 1][(nt & 1) * 2]);
        // ---- ks = 1 (reuse ah/al/bl arrays; prior values dead) ----
        LDMATRIX_X4(ah[0], (aHiAdr[0] + so) ^ 32);
        LDMATRIX_X4(ah[1], (aHiAdr[1] + so) ^ 32);
        // HH1 (al loads under cover)
        LDMATRIX_X4(al[0], (aLoAdr[0] + so) ^ 32);
#pragma unroll
        for (int nt = 0; nt < 8; nt++)
            MMA16816(c[0][nt], ah[0], &bh1[nt >> 1][(nt & 1) * 2]);
        LDMATRIX_X4(al[1], (aLoAdr[1] + so) ^ 32);
#pragma unroll
        for (int nt = 0; nt < 8; nt++)
            MMA16816(c[1][nt], ah[1], &bh1[nt >> 1][(nt & 1) * 2]);
        // LH1 (bl loads under cover)
        LDMATRIX_X4(bl[0], (bLoAdr[0] + so) ^ 32);
        LDMATRIX_X4(bl[1], (bLoAdr[1] + so) ^ 32);
#pragma unroll
        for (int nt = 0; nt < 8; nt++)
            MMA16816(c[0][nt], al[0], &bh1[nt >> 1][(nt & 1) * 2]);
        LDMATRIX_X4(bl[2], (bLoAdr[2] + so) ^ 32);
        LDMATRIX_X4(bl[3], (bLoAdr[3] + so) ^ 32);
#pragma unroll
        for (int nt = 0; nt < 8; nt++)
            MMA16816(c[1][nt], al[1], &bh1[nt >> 1][(nt & 1) * 2]);
        // HL1
#pragma unroll
        for (int nt = 0; nt < 8; nt++)
            MMA16816(c[0][nt], ah[0], &bl[nt >> 1][(nt & 1) * 2]);
#pragma unroll
        for (int nt = 0; nt < 8; nt++)
            MMA16816(c[1][nt], ah[1], &bl[nt >> 1][(nt & 1) * 2]);
    };

    issue_copy(0, 0);
    issue_copy(1, 1);
#pragma unroll
    for (int s = 0; s < NSTAGE; s++) {
        if (s == NSTAGE - 1) { CP_WAIT(0); } else { CP_WAIT(1); }
        __syncthreads();
        if (s + 2 < NSTAGE) issue_copy(s + 2, (uint32_t)((s + 2) % PIPE));
        compute_stage((uint32_t)(s % PIPE) * STG_B);
    }

    // ---- epilogue: x1 = c + b1 -> gmem ----
    const int lr = l >> 2, lq = (l & 3) * 2;
    float bb[8][2];
#pragma unroll
    for (int nt = 0; nt < 8; nt++) {
        bb[nt][0] = __ldg(&b1[h0 + wn * 64 + nt * 8 + lq]);
        bb[nt][1] = __ldg(&b1[h0 + wn * 64 + nt * 8 + lq + 1]);
    }
#pragma unroll
    for (int mt = 0; mt < 2; mt++)
#pragma unroll
        for (int rr = 0; rr < 2; rr++) {
            const size_t grow = (size_t)(b0 + wm * 32 + mt * 16 + rr * 8 + lr) * NHc;
#pragma unroll
            for (int nt = 0; nt < 8; nt++) {
                const int gcol = h0 + wn * 64 + nt * 8 + lq;
                float2 v = make_float2(c[mt][nt][rr * 2 + 0] + bb[nt][0],
                                       c[mt][nt][rr * 2 + 1] + bb[nt][1]);
                *(float2*)&g_x1[grow + gcol] = v;
            }
        }
}

// ---------------- K3: LIF recurrence (f32x2) + W2 reduce ----------------
__device__ __forceinline__ u64 pk2(float lo, float hi) {
    u64 r;
    asm("mov.b64 %0, {%1, %2};" : "=l"(r) : "f"(lo), "f"(hi));
    return r;
}
__device__ __forceinline__ void upk2(u64 v, float& lo, float& hi) {
    asm("mov.b64 {%0, %1}, %2;" : "=f"(lo), "=f"(hi) : "l"(v));
}
__device__ __forceinline__ u64 fma2(u64 a, u64 b, u64 c) {
    u64 d;
    asm("fma.rn.f32x2 %0, %1, %2, %3;" : "=l"(d) : "l"(a), "l"(b), "l"(c));
    return d;
}
__device__ __forceinline__ void add2(u64& d, u64 a) {
    asm("add.rn.f32x2 %0, %0, %1;" : "+l"(d) : "l"(a));
}
__device__ __forceinline__ float fset_gt(float a, float b) {
    float s;
    asm("set.gt.f32.f32 %0, %1, %2;" : "=f"(s) : "f"(a), "f"(b));
    return s;
}

// block = 256 threads = 8 warps = 2 batch rows (4 warps x 256 cols each).
// Deterministic smem reduction, direct store of sum + b2 (no init kernel, no atomics).
__global__ void __launch_bounds__(256)
snn_lif_kernel(const float* __restrict__ W2,
               const float* __restrict__ beta_p,
               const float* __restrict__ thr,
               const float* __restrict__ b2,
               float* __restrict__ out) {
    __shared__ float red[8];
    const int tid  = threadIdx.x;
    const int wid  = tid >> 5;
    const int lane = tid & 31;
    const int b    = blockIdx.x * 2 + (wid >> 2);
    const int q    = wid & 3;
    const int hb   = q * 256 + lane * 8;

    const float beta = fminf(fmaxf(__ldg(beta_p), 0.0f), 1.0f);
    const u64 beta2 = pk2(beta, beta);

    float x1[8], thv[8];
    const float* px = g_x1 + (size_t)b * NHc + hb;
    *(float4*)&x1[0]  = *(const float4*)(px);
    *(float4*)&x1[4]  = *(const float4*)(px + 4);
    *(float4*)&thv[0] = *(const float4*)(thr + hb);
    *(float4*)&thv[4] = *(const float4*)(thr + hb + 4);

    u64 x12[4], nth2[4], m2[4], cnt2[4];
#pragma unroll
    for (int p = 0; p < 4; p++) {
        x12[p]  = pk2(x1[2 * p], x1[2 * p + 1]);
        nth2[p] = pk2(-thv[2 * p], -thv[2 * p + 1]);
        cnt2[p] = pk2(0.0f, 0.0f);
        // step 1 from mem0 = 0: reset = H(0 - thr)
        u64 sv = pk2(fset_gt(0.0f, thv[2 * p]), fset_gt(0.0f, thv[2 * p + 1]));
        m2[p] = fma2(sv, nth2[p], x12[p]);
    }
#pragma unroll 4
    for (int t = 1; t < NSTEPS; t++) {
#pragma unroll
        for (int p = 0; p < 4; p++) {
            float ma, mb;
            upk2(m2[p], ma, mb);
            u64 sv = pk2(fset_gt(ma, thv[2 * p]), fset_gt(mb, thv[2 * p + 1]));
            add2(cnt2[p], sv);
            m2[p] = fma2(beta2, m2[p], fma2(sv, nth2[p], x12[p]));
        }
    }
    float acc = 0.0f;
#pragma unroll
    for (int p = 0; p < 4; p++) {
        float ma, mb;
        upk2(m2[p], ma, mb);
        u64 sv = pk2(fset_gt(ma, thv[2 * p]), fset_gt(mb, thv[2 * p + 1]));
        add2(cnt2[p], sv);
        float ca, cb;
        upk2(cnt2[p], ca, cb);
        acc = fmaf(ca, __ldg(&W2[hb + 2 * p]), acc);
        acc = fmaf(cb, __ldg(&W2[hb + 2 * p + 1]), acc);
    }
#pragma unroll
    for (int off = 16; off > 0; off >>= 1)
        acc += __shfl_down_sync(0xffffffffu, acc, off);
    if (lane == 0) red[wid] = acc;
    __syncthreads();
    if (tid < 2)
        out[blockIdx.x * 2 + tid] =
            red[tid * 4] + red[tid * 4 + 1] + red[tid * 4 + 2] + red[tid * 4 + 3]
            + __ldg(b2);
}

extern "C" void kernel_launch(void* const* d_in, const int* in_sizes, int n_in,
                              void* d_out, int out_size) {
    const float* x    = (const float*)d_in[0];
    const float* W1   = (const float*)d_in[1];
    const float* b1   = (const float*)d_in[2];
    const float* W2   = (const float*)d_in[3];
    const float* b2   = (const float*)d_in[4];
    const float* beta = (const float*)d_in[5];
    const float* thr  = (const float*)d_in[6];
    float* out = (float*)d_out;

    const int B = in_sizes[0] / NIc;  // 32768

    __half *xhi, *xlo, *whi, *wlo;
    cudaGetSymbolAddress((void**)&xhi, g_xhi);
    cudaGetSymbolAddress((void**)&xlo, g_xlo);
    cudaGetSymbolAddress((void**)&whi, g_whi);
    cudaGetSymbolAddress((void**)&wlo, g_wlo);

    const int nx4 = B * NIc / 4;
    const int nw4 = NHc * NIc / 4;
    cvt_kernel<<<(nx4 + 255) / 256, 256>>>(x, xhi, xlo, nx4);
    cvt_kernel<<<(nw4 + 255) / 256, 256>>>(W1, whi, wlo, nw4);

    cudaFuncSetAttribute(snn_gemm_kernel,
                         cudaFuncAttributeMaxDynamicSharedMemorySize, SMEM_TOTAL);

    dim3 grid(NHc / BN, B / BM);   // (8, 256)
    snn_gemm_kernel<<<grid, 256, SMEM_TOTAL>>>(b1);

    snn_lif_kernel<<<B / 2, 256>>>(W2, beta, thr, b2, out);
}